// round 6
// baseline (speedup 1.0000x reference)
#include <cuda_runtime.h>

// Fixed shapes: B=64, C=3, H=W=256
#define NCAT    5
#define NB      64
#define E_ELEM  196608           // scalar positions per sample
#define TPB     256
#define NBLOCKS (E_ELEM / TPB)   // 768
#define NPART   15               // 5 scaled, 5 abs, 5 un-total
#define NPAD    16
#define EPSF    1e-6f

__device__ float g_part[NBLOCKS * NPAD];
__device__ int   g_done = 0;     // self-resetting last-block counter

// ---------------------------------------------------------------------------
// Single kernel, perfectly balanced: thread = scalar position j; iterates all
// 64 samples in category-sorted order; per-category flush writes to smem.
// ---------------------------------------------------------------------------
__global__ void __launch_bounds__(TPB)
k_fused(const float* __restrict__ restored,
        const float* __restrict__ clean,
        const int*   __restrict__ de_id,
        const float* __restrict__ un,
        float*       __restrict__ out) {
    __shared__ int   s_id[NB];
    __shared__ int   s_off[NB];          // element offsets (b*E), cat-sorted
    __shared__ int   s_start[NCAT + 1];
    __shared__ int   s_cnt[NCAT];
    __shared__ float s_invc[NCAT];
    __shared__ float sred[NPART][TPB];
    __shared__ int   s_last;

    const int tid = threadIdx.x;

    // ---- parallel setup: clamp ids, rank-sort, counts, starts ----
    if (tid < NB) {
        int c = de_id[tid];
        s_id[tid] = c < 0 ? 0 : (c >= NCAT ? NCAT - 1 : c);
    }
    __syncthreads();
    if (tid < NB) {
        const int myc = s_id[tid];
        int rank = 0;
#pragma unroll
        for (int b = 0; b < NB; ++b) {
            int cb = s_id[b];
            rank += (cb < myc) || (cb == myc && b < tid);
        }
        s_off[rank] = tid * E_ELEM;
    }
    if (tid >= NB && tid < NB + NCAT) {          // counts + invc on 5 threads
        int c = tid - NB, cnt = 0;
#pragma unroll
        for (int b = 0; b < NB; ++b) cnt += (s_id[b] == c);
        s_cnt[c]  = cnt;
        s_invc[c] = 1.0f / (float)(cnt > 0 ? cnt : 1);
    }
    if (tid >= NB + NCAT && tid < NB + NCAT + NCAT + 1) {   // starts on 6 threads
        int c = tid - NB - NCAT, st = 0;
#pragma unroll
        for (int b = 0; b < NB; ++b) st += (s_id[b] < c);
        s_start[c] = st;
    }
    __syncthreads();

    // ---- main loop: 64 iterations total, 5 category segments ----
    const int j = blockIdx.x * TPB + tid;
    const float* __restrict__ rp = restored;
    const float* __restrict__ cp = clean;
    const float* __restrict__ up = un;

#pragma unroll
    for (int c = 0; c < NCAT; ++c) {
        float U = 0.0f, A = 0.0f;
        int k  = s_start[c];
        const int ke = s_start[c + 1];
#pragma unroll 4
        for (; k < ke; ++k) {
            int off = s_off[k] + j;
            float u  = up[off];
            float r  = rp[off];
            float cl = cp[off];
            U += u;
            A += fabsf(cl - r);
        }
        float s = 1.0f / (U * s_invc[c] + EPSF);
        sred[c][tid]      = A * s;   // scaled
        sred[5 + c][tid]  = A;       // abs
        sred[10 + c][tid] = U;       // un total
    }

    // ---- block reduction of 15 values ----
    __syncthreads();
#pragma unroll
    for (int st = TPB / 2; st > 0; st >>= 1) {
        if (tid < st) {
#pragma unroll
            for (int v = 0; v < NPART; ++v) sred[v][tid] += sred[v][tid + st];
        }
        __syncthreads();
    }
    if (tid < NPART) g_part[blockIdx.x * NPAD + tid] = sred[tid][0];

    // ---- last-block finalize (deterministic fixed-order reads) ----
    __syncthreads();
    __threadfence();
    if (tid == 0) s_last = (atomicAdd(&g_done, 1) == NBLOCKS - 1);
    __syncthreads();
    if (!s_last) return;
    __threadfence();

    {
        // 768 rows / 256 threads = 3 rows each (NPAD=16 floats = 4 float4)
        float acc[NPART];
#pragma unroll
        for (int v = 0; v < NPART; ++v) acc[v] = 0.0f;
        const float4* gp4 = reinterpret_cast<const float4*>(g_part);
        int base = tid * 3 * (NPAD / 4);
#pragma unroll
        for (int r = 0; r < 3; ++r) {
            float4 q0 = __ldcg(gp4 + base + 0);
            float4 q1 = __ldcg(gp4 + base + 1);
            float4 q2 = __ldcg(gp4 + base + 2);
            float4 q3 = __ldcg(gp4 + base + 3);
            base += NPAD / 4;
            acc[0] += q0.x;  acc[1] += q0.y;  acc[2]  += q0.z;  acc[3]  += q0.w;
            acc[4] += q1.x;  acc[5] += q1.y;  acc[6]  += q1.z;  acc[7]  += q1.w;
            acc[8] += q2.x;  acc[9] += q2.y;  acc[10] += q2.z;  acc[11] += q2.w;
            acc[12] += q3.x; acc[13] += q3.y; acc[14] += q3.z;
        }
#pragma unroll
        for (int v = 0; v < NPART; ++v) sred[v][tid] = acc[v];
        __syncthreads();
#pragma unroll
        for (int st = TPB / 2; st > 0; st >>= 1) {
            if (tid < st) {
#pragma unroll
                for (int v = 0; v < NPART; ++v) sred[v][tid] += sred[v][tid + st];
            }
            __syncthreads();
        }
        if (tid == 0) {
            const float Ef = (float)E_ELEM;
            float totalsum = 0.0f, cum_sc = 0.0f, cumN = 0.0f;
            int num_ne = 0;
#pragma unroll
            for (int c = 0; c < NCAT; ++c) if (s_cnt[c] > 0) num_ne++;
#pragma unroll
            for (int c = 0; c < NCAT; ++c) {
                int   cnt  = s_cnt[c];
                bool  ne   = cnt > 0;
                float safe = (float)(cnt > 0 ? cnt : 1);
                float S_sc = sred[c][0];
                float S_ab = sred[5 + c][0];
                float S_un = sred[10 + c][0];

                cum_sc += S_sc;
                cumN   += (float)cnt * Ef;
                float cum_l1 = cum_sc / fmaxf(cumN, 1.0f);
                float un_num = S_un / (safe * Ef) + EPSF;
                float bn     = ne ? 2.0f * logf(un_num) : 0.0f;
                float unc    = ne ? cum_l1 : 0.0f;
                float old_l  = ne ? S_ab / (safe * Ef) : 0.0f;
                float cat_l  = unc + bn;
                totalsum += cat_l;

                out[1 + c]  = cat_l;
                out[6 + c]  = old_l;
                out[11 + c] = bn;
                out[16 + c] = unc;
            }
            out[0] = totalsum / (float)(num_ne > 0 ? num_ne : 1);
            g_done = 0;   // self-reset for graph replay
        }
    }
}

// ---------------------------------------------------------------------------
extern "C" void kernel_launch(void* const* d_in, const int* in_sizes, int n_in,
                              void* d_out, int out_size) {
    const float* restored = (const float*)d_in[0];
    const float* clean    = (const float*)d_in[1];
    const int*   de_id    = (const int*)d_in[2];
    const float* un       = (const float*)d_in[3];
    float*       out      = (float*)d_out;

    k_fused<<<NBLOCKS, TPB>>>(restored, clean, de_id, un, out);
}